// round 16
// baseline (speedup 1.0000x reference)
#include <cuda_runtime.h>
#include <math.h>

#define K_SIZE 41

// Period-41 table of float4 write patterns, produced by prep kernel.
__device__ float4 g_pat[K_SIZE];

// ---------------------------------------------------------------------------
// Prep: 1 block. Compute padded window, masked circular max -> base[41],
// expand to float4 pattern table, and write the <=3 tail scalars of out.
// ---------------------------------------------------------------------------
__global__ void flatdil_prep_kernel(const float* __restrict__ in,
                                    const float* __restrict__ scale_p,
                                    float* __restrict__ out,
                                    long long n)
{
    __shared__ float s_pad[K_SIZE];
    __shared__ float s_base[K_SIZE];

    const int t = threadIdx.x;
    const float scale = *scale_p;

    // Python: missing = K_SIZE - n; a = -(missing // 2 + 2)   (floor division)
    const long long missing = (long long)K_SIZE - n;
    const long long a = -((missing >> 1) + 2);   // arithmetic shift == floor div by 2

    if (t < K_SIZE) {
        s_pad[t] = in[a + (long long)t];
    }
    __syncthreads();

    if (t < K_SIZE) {
        float acc = -INFINITY;
        #pragma unroll
        for (int j = 0; j < K_SIZE; ++j) {
            // z[j] = -20 + j (linspace(-20,20,41) has exact unit step)
            const float zj = (float)(j - 20);
            if (fabsf(zj) <= scale) {
                int idx = t + j;
                if (idx >= K_SIZE) idx -= K_SIZE;
                acc = fmaxf(acc, s_pad[idx]);
            }
        }
        s_base[t] = acc;
    }
    __syncthreads();

    if (t < K_SIZE) {
        // g_pat[p] covers output floats 4p..4p+3 (pattern period in float4s = 41)
        int i0 = (4 * t) % K_SIZE;
        int i1 = i0 + 1; if (i1 >= K_SIZE) i1 -= K_SIZE;
        int i2 = i1 + 1; if (i2 >= K_SIZE) i2 -= K_SIZE;
        int i3 = i2 + 1; if (i3 >= K_SIZE) i3 -= K_SIZE;
        float4 v;
        v.x = s_base[i0];
        v.y = s_base[i1];
        v.z = s_base[i2];
        v.w = s_base[i3];
        g_pat[t] = v;
    }

    // Tail: elements not covered by the float4 writer (<= 3 of them)
    if (t == 0) {
        long long n4 = n >> 2;          // number of full float4s
        for (long long k = n4 * 4; k < n; ++k) {
            out[k] = s_base[(int)(k % K_SIZE)];
        }
    }
}

// ---------------------------------------------------------------------------
// Writer: one STG.128 per thread. Pattern staged in shared (656 B) so global
// read traffic is ~21 MB total instead of 537 MB.
// ---------------------------------------------------------------------------
__global__ void __launch_bounds__(256)
flatdil_write_kernel(float4* __restrict__ out4, unsigned int n4)
{
    __shared__ float4 s_pat[K_SIZE];
    const unsigned int t = threadIdx.x;
    if (t < K_SIZE) s_pat[t] = g_pat[t];
    __syncthreads();

    const unsigned int i = blockIdx.x * 256u + t;
    if (i < n4) {
        out4[i] = s_pat[i % K_SIZE];
    }
}

// ---------------------------------------------------------------------------
extern "C" void kernel_launch(void* const* d_in, const int* in_sizes, int n_in,
                              void* d_out, int out_size)
{
    const float* in      = (const float*)d_in[0];
    const float* scale_p = (const float*)d_in[1];
    float* out           = (float*)d_out;

    const long long n  = (long long)in_sizes[0];
    const long long n4 = n >> 2;

    flatdil_prep_kernel<<<1, 64>>>(in, scale_p, out, n);

    if (n4 > 0) {
        unsigned int blocks = (unsigned int)((n4 + 255) / 256);
        flatdil_write_kernel<<<blocks, 256>>>((float4*)out, (unsigned int)n4);
    }
}